// round 15
// baseline (speedup 1.0000x reference)
#include <cuda_runtime.h>
#include <cuda_bf16.h>
#include <math.h>
#include <stdint.h>

// Problem dims
#define Bv 4096
#define Tt 28
#define In 28
#define Hh 512
#define Gg 1536   // 3*H
#define H2 1024   // 2*H

#define BH 2097152      // B*H
#define BG 6291456      // B*3H
#define MT 114688       // B*T

// ---------------- scratch (static device allocations; allowed) ----------------
__device__ float g_gxA[176160768];   // B*T*3H : gx layer0 fwd, reused as gx layer1 fwd
__device__ float g_gxB[176160768];   // B*T*3H : gx layer0 bwd
__device__ float g_h[2 * 2097152];   // layer0 fwd/bwd hidden (fp32 state)
__device__ float g_h1[2097152];      // layer1 fwd hidden (fp32 state)
__device__ float g_h1b[2097152];     // layer1 bwd hidden (one step)
__device__ float g_gx1b[6291456];    // layer1 bwd gx at t=T-1
__device__ float g_z1[1048576];      // B*256 fc1 output

// bf16 operands. A-side stores hi+lo only; GEMMs synthesize [hi|hi|lo] virtually.
// W-side physically stacked [Wh|Wl|Wh], natural row order.
__device__ __nv_bfloat16 g_xs[14680064];     // x stacked [B*T,128] physical [hi|hi|lo|0]
__device__ __nv_bfloat16 g_ws[17694720];     // weights arena (stacked)
__device__ __nv_bfloat16 g_y0h[117440512];   // y0 hi [B*T,1024]
__device__ __nv_bfloat16 g_y0l[117440512];   // y0 lo [B*T,1024]
__device__ __nv_bfloat16 g_hh[2*2*2097152];  // l0 h hi, [buf][dir][B,512]
__device__ __nv_bfloat16 g_hl[2*2*2097152];  // l0 h lo
__device__ __nv_bfloat16 g_h1h[2*2097152];   // l1 h hi, [buf][B,512]
__device__ __nv_bfloat16 g_h1l[2*2097152];   // l1 h lo
__device__ __nv_bfloat16 g_lasth[4194304];   // concat hi [B,1024]
__device__ __nv_bfloat16 g_lastl[4194304];   // concat lo [B,1024]

// Weight arena offsets (bf16 elements)
#define WS_IH_L0   0          // 1536 x 128
#define WS_IH_L0R  196608
#define WS_HH_L0   393216     // 1536 x 1536
#define WS_HH_L0R  2752512
#define WS_HH_L1   5111808
#define WS_IH_L1   7471104    // 1536 x 3072
#define WS_IH_L1R  12189696
#define WS_FC1     16908288   // 256 x 3072

// ============================================================================
// PTX helpers (baseline sm_80+ features; valid on .target sm_103)
// ============================================================================
__device__ __forceinline__ uint32_t smem_u32(const void* p) {
    uint32_t a;
    asm("{ .reg .u64 t; cvta.to.shared.u64 t, %1; cvt.u32.u64 %0, t; }" : "=r"(a) : "l"(p));
    return a;
}
__device__ __forceinline__ void cp16(uint32_t s, const void* g) {
    asm volatile("cp.async.cg.shared.global [%0], [%1], 16;" :: "r"(s), "l"(g));
}
__device__ __forceinline__ void ldsm4(uint32_t* r, uint32_t a) {
    asm volatile("ldmatrix.sync.aligned.m8n8.x4.shared.b16 {%0,%1,%2,%3}, [%4];"
                 : "=r"(r[0]), "=r"(r[1]), "=r"(r[2]), "=r"(r[3]) : "r"(a));
}
__device__ __forceinline__ void mma16816(float* d, const uint32_t* a, uint32_t b0, uint32_t b1) {
    asm volatile("mma.sync.aligned.m16n8k16.row.col.f32.bf16.bf16.f32 "
                 "{%0,%1,%2,%3}, {%4,%5,%6,%7}, {%8,%9}, {%0,%1,%2,%3};"
                 : "+f"(d[0]), "+f"(d[1]), "+f"(d[2]), "+f"(d[3])
                 : "r"(a[0]), "r"(a[1]), "r"(a[2]), "r"(a[3]), "r"(b0), "r"(b1));
}

__device__ __forceinline__ float sigmoidf_(float x) { return 1.f / (1.f + expf(-x)); }
__device__ __forceinline__ void split_bf16(float v, __nv_bfloat16& h, __nv_bfloat16& l) {
    h = __float2bfloat16(v);
    l = __float2bfloat16(v - __bfloat162float(h));
}

// ============================================================================
// Pipelined bf16 GEMM (input projections / fc1): C = A' @ W'^T + bias
// Virtual-stacked A: seg = k>>kshift; seg<2 -> Ahi[k&mask], seg2 -> Alo.
// 128x128x64 tiles, 3-stage cp.async, 8 warps (64x32 each), 2 CTA/SM.
// (R10-proven shape — do not disturb.)
// ============================================================================
struct MOp {
    const __nv_bfloat16 *Ahi, *Alo;
    const __nv_bfloat16 *W;
    const float *bias;
    float *C;
    int lda;
    int koff;
};

#define STAGE_B 32768
#define SMEM_SZ (3 * STAGE_B)

__device__ __forceinline__ void prefetch_stage(const MOp& op, uint32_t sb, int c,
                                               int bm, int bn, int ldw,
                                               int kshift, int kmask, int tid)
{
    const int st = c % 3;
    const uint32_t abase = sb + st * STAGE_B;
    const uint32_t wbase = abase + 16384;
    const int kc0 = c * 64;
#pragma unroll
    for (int i = 0; i < 4; i++) {
        int v = tid + i * 256;
        int row = v >> 3, ch = v & 7;
        int kg  = op.koff + kc0 + ch * 8;
        int seg = kg >> kshift;
        int off = kg & kmask;
        const __nv_bfloat16* g = (seg < 2 ? op.Ahi : op.Alo)
                               + (size_t)(bm + row) * op.lda + off;
        cp16(abase + row * 128 + ((ch ^ (row & 7)) << 4), g);
    }
#pragma unroll
    for (int i = 0; i < 4; i++) {
        int v = tid + i * 256;
        int row = v >> 3, ch = v & 7;
        const __nv_bfloat16* g = op.W + (size_t)(bn + row) * ldw + kc0 + ch * 8;
        cp16(wbase + row * 128 + ((ch ^ (row & 7)) << 4), g);
    }
    asm volatile("cp.async.commit_group;");
}

__global__ void __launch_bounds__(256, 2) mma_gemm(MOp op0, MOp op1,
                                                   int ldw, int ldc, int K, int kshift)
{
    extern __shared__ char smem[];
    MOp op = (blockIdx.z == 0) ? op0 : op1;
    const uint32_t sb = smem_u32(smem);
    const int kmask = (kshift >= 30) ? 0x3FFFFFFF : ((1 << kshift) - 1);
    const int tid  = threadIdx.x;
    const int wid  = tid >> 5;
    const int lane = tid & 31;
    const int bm = blockIdx.y * 128;
    const int bn = blockIdx.x * 128;
    const int wm = (wid >> 2) * 64;
    const int wn = (wid & 3) * 32;

    float acc[4][4][4];
#pragma unroll
    for (int i = 0; i < 4; i++)
#pragma unroll
        for (int j = 0; j < 4; j++)
#pragma unroll
            for (int r = 0; r < 4; r++) acc[i][j][r] = 0.f;

    const int nc = K >> 6;

    prefetch_stage(op, sb, 0, bm, bn, ldw, kshift, kmask, tid);
    if (nc > 1) prefetch_stage(op, sb, 1, bm, bn, ldw, kshift, kmask, tid);

    for (int c = 0; c < nc; c++) {
        if (c + 2 < nc) {
            prefetch_stage(op, sb, c + 2, bm, bn, ldw, kshift, kmask, tid);
            asm volatile("cp.async.wait_group 2;");
        } else if (c + 1 < nc) {
            asm volatile("cp.async.wait_group 1;");
        } else {
            asm volatile("cp.async.wait_group 0;");
        }
        __syncthreads();

        const int st = c % 3;
        const uint32_t abase = sb + st * STAGE_B;
        const uint32_t wbase = abase + 16384;

#pragma unroll
        for (int kk = 0; kk < 4; kk++) {
            uint32_t a[4][4], b[2][4];
#pragma unroll
            for (int mf = 0; mf < 4; mf++) {
                int r   = wm + mf * 16 + ((lane >> 3) & 1) * 8 + (lane & 7);
                int cch = kk * 2 + (lane >> 4);
                ldsm4(a[mf], abase + r * 128 + ((cch ^ (r & 7)) << 4));
            }
#pragma unroll
            for (int nf = 0; nf < 2; nf++) {
                int r   = wn + nf * 16 + ((lane >> 4) & 1) * 8 + (lane & 7);
                int cch = kk * 2 + ((lane >> 3) & 1);
                ldsm4(b[nf], wbase + r * 128 + ((cch ^ (r & 7)) << 4));
            }
#pragma unroll
            for (int mf = 0; mf < 4; mf++)
#pragma unroll
                for (int nt = 0; nt < 4; nt++)
                    mma16816(acc[mf][nt], a[mf],
                             b[nt >> 1][(nt & 1) * 2], b[nt >> 1][(nt & 1) * 2 + 1]);
        }
        __syncthreads();
    }

#pragma unroll
    for (int mf = 0; mf < 4; mf++) {
        int row = bm + wm + mf * 16 + (lane >> 2);
#pragma unroll
        for (int nt = 0; nt < 4; nt++) {
            int col = bn + wn + nt * 8 + (lane & 3) * 2;
            float b0 = op.bias[col], b1 = op.bias[col + 1];
            float2 v0 = make_float2(acc[mf][nt][0] + b0, acc[mf][nt][1] + b1);
            float2 v1 = make_float2(acc[mf][nt][2] + b0, acc[mf][nt][3] + b1);
            *(float2*)(op.C + (size_t)row * ldc + col) = v0;
            *(float2*)(op.C + (size_t)(row + 8) * ldc + col) = v1;
        }
    }
}

// ============================================================================
// Gate-fused recurrent step, NATURAL weight layout.
// CTA tile: 128 rows x 384 cols where the 384 cols are the SAME 128 h-units
// across all 3 gates (W rows {g*512 + ng*128 + r}). Full GRU update in the
// epilogue -> gh never hits DRAM, no separate gate kernel.
// K=1536 virtual [hi|hi|lo]. 8 warps as 2x4, warp tile 64x96. 1 CTA/SM.
// ============================================================================
struct R3Op {
    const __nv_bfloat16 *Ahi, *Alo;  // h hi/lo (natural, ld 512)
    const __nv_bfloat16 *W;          // stacked Whh [1536,1536] natural rows
    const float *bhh;                // [1536]
    const float *gx;                 // [B,T,1536] natural
    float *h;                        // [B,512] in/out
    __nv_bfloat16 *hho, *hlo;        // out hi/lo (natural)
    __nv_bfloat16 *y0h, *y0l;        // [B,T,1024] or nullptr
    int t, y0off;
};

#define R3_STAGE 65536               // A 16KB + 3x W 16KB
#define R3_SMEM  (3 * R3_STAGE)      // 196608 (= 128*384*4 exactly, reused by epilogue)

__device__ __forceinline__ void r3_prefetch(const R3Op& s, uint32_t sb, int c,
                                            int bm, int ng, int tid)
{
    const int st = c % 3;
    const uint32_t abase = sb + st * R3_STAGE;
    const uint32_t wbase = abase + 16384;
    const int kc0 = c * 64;
#pragma unroll
    for (int i = 0; i < 4; i++) {           // A: 128 rows x 8 chunks
        int v = tid + i * 256;
        int row = v >> 3, ch = v & 7;
        int kg  = kc0 + ch * 8;
        int seg = kg >> 9;
        int off = kg & 511;
        const __nv_bfloat16* g = (seg < 2 ? s.Ahi : s.Alo) + (size_t)(bm + row) * 512 + off;
        cp16(abase + row * 128 + ((ch ^ (row & 7)) << 4), g);
    }
#pragma unroll
    for (int i = 0; i < 12; i++) {          // W: 3 gates x 128 rows x 8 chunks
        int v = tid + i * 256;              // 0..3071
        int gg = v >> 10, r = (v >> 3) & 127, ch = v & 7;
        const __nv_bfloat16* g = s.W + (size_t)(gg * 512 + ng * 128 + r) * 1536 + kc0 + ch * 8;
        cp16(wbase + gg * 16384 + r * 128 + ((ch ^ (r & 7)) << 4), g);
    }
    asm volatile("cp.async.commit_group;");
}

__global__ void __launch_bounds__(256, 1) rec3_step(R3Op s0, R3Op s1)
{
    extern __shared__ char smem[];
    R3Op s = (blockIdx.z == 0) ? s0 : s1;
    const uint32_t sb = smem_u32(smem);
    const int tid  = threadIdx.x;
    const int wid  = tid >> 5;
    const int lane = tid & 31;
    const int ng = blockIdx.x;          // 0..3 over 128-unit groups
    const int bm = blockIdx.y * 128;
    const int wm = (wid >> 2) * 64;     // 2 warp rows
    const int wc0 = (wid & 3) * 96;     // 4 warp cols (96 wide)

    float acc[4][12][4];
#pragma unroll
    for (int i = 0; i < 4; i++)
#pragma unroll
        for (int j = 0; j < 12; j++)
#pragma unroll
            for (int r = 0; r < 4; r++) acc[i][j][r] = 0.f;

    const int nc = 24;   // K=1536 / 64

    r3_prefetch(s, sb, 0, bm, ng, tid);
    r3_prefetch(s, sb, 1, bm, ng, tid);

    for (int c = 0; c < nc; c++) {
        if (c + 2 < nc) {
            r3_prefetch(s, sb, c + 2, bm, ng, tid);
            asm volatile("cp.async.wait_group 2;");
        } else if (c + 1 < nc) {
            asm volatile("cp.async.wait_group 1;");
        } else {
            asm volatile("cp.async.wait_group 0;");
        }
        __syncthreads();

        const int st = c % 3;
        const uint32_t abase = sb + st * R3_STAGE;
        const uint32_t wbase = abase + 16384;

#pragma unroll
        for (int kk = 0; kk < 4; kk++) {
            uint32_t a[4][4], b[6][4];
#pragma unroll
            for (int mf = 0; mf < 4; mf++) {
                int r   = wm + mf * 16 + ((lane >> 3) & 1) * 8 + (lane & 7);
                int cch = kk * 2 + (lane >> 4);
                ldsm4(a[mf], abase + r * 128 + ((cch ^ (r & 7)) << 4));
            }
#pragma unroll
            for (int f = 0; f < 6; f++) {
                int cglob = wc0 + f * 16 + ((lane >> 4) & 1) * 8 + (lane & 7);
                int gg = cglob >> 7;        // gate index (16-col blocks never straddle 128)
                int r  = cglob & 127;
                int cch = kk * 2 + ((lane >> 3) & 1);
                ldsm4(b[f], wbase + gg * 16384 + r * 128 + ((cch ^ (r & 7)) << 4));
            }
#pragma unroll
            for (int mf = 0; mf < 4; mf++)
#pragma unroll
                for (int nf = 0; nf < 12; nf++)
                    mma16816(acc[mf][nf], a[mf],
                             b[nf >> 1][(nf & 1) * 2], b[nf >> 1][(nf & 1) * 2 + 1]);
        }
        __syncthreads();
    }

    // stage acc tile (128 x 384 fp32 = exactly the 192KB stage memory)
    float* sg = (float*)smem;
#pragma unroll
    for (int mf = 0; mf < 4; mf++) {
        int row0 = wm + mf * 16 + (lane >> 2);
#pragma unroll
        for (int nf = 0; nf < 12; nf++) {
            int col = wc0 + nf * 8 + (lane & 3) * 2;
            sg[row0 * 384 + col]           = acc[mf][nf][0];
            sg[row0 * 384 + col + 1]       = acc[mf][nf][1];
            sg[(row0 + 8) * 384 + col]     = acc[mf][nf][2];
            sg[(row0 + 8) * 384 + col + 1] = acc[mf][nf][3];
        }
    }
    __syncthreads();

    // fused GRU gate: 128 rows x 128 h-units (cols 0-127=r, 128-255=z, 256-383=n)
    for (int idx = tid; idx < 16384; idx += 256) {
        const int row = idx >> 7;
        const int u   = idx & 127;
        const int brow = bm + row;
        const int jg   = ng * 128 + u;

        float ar = sg[row * 384 + u];
        float az = sg[row * 384 + 128 + u];
        float an = sg[row * 384 + 256 + u];

        const float* gxr = s.gx + ((size_t)brow * Tt + s.t) * Gg;
        float r = sigmoidf_(gxr[jg] + ar + s.bhh[jg]);
        float z = sigmoidf_(gxr[512 + jg] + az + s.bhh[512 + jg]);
        float n = tanhf(gxr[1024 + jg] + r * (an + s.bhh[1024 + jg]));

        const size_t hidx = (size_t)brow * 512 + jg;
        float hn = (1.f - z) * n + z * s.h[hidx];
        s.h[hidx] = hn;

        __nv_bfloat16 hh, hl;
        split_bf16(hn, hh, hl);
        s.hho[hidx] = hh;
        s.hlo[hidx] = hl;
        if (s.y0h) {
            const size_t yi = ((size_t)brow * Tt + s.t) * 1024 + s.y0off + jg;
            s.y0h[yi] = hh;
            s.y0l[yi] = hl;
        }
    }
}

// ============================================================================
// init: zero all state in one launch
// ============================================================================
#define ZF  (3 * BH)              // g_h (2BH) + g_h1 (BH)
#define ZB  (6 * BH)              // bf16 mirrors buf0
#define ZTOT (ZF + ZB)

__global__ void zero_all(void)
{
    long long i = (long long)blockIdx.x * blockDim.x + threadIdx.x;
    if (i >= ZTOT) return;
    if (i < ZF) {
        if (i < 2 * BH) g_h[i] = 0.f;
        else            g_h1[i - 2 * BH] = 0.f;
    } else {
        long long k = i - ZF;
        __nv_bfloat16 z = __float2bfloat16(0.f);
        if (k < 2 * BH)      g_hh[k] = z;
        else if (k < 4 * BH) g_hl[k - 2 * BH] = z;
        else if (k < 5 * BH) g_h1h[k - 4 * BH] = z;
        else                 g_h1l[k - 5 * BH] = z;
    }
}

// ============================================================================
// conversion: all hi/lo stacking jobs in one launch (block-offset job table)
// per-seg mode: 0=hi, 1=lo, 2=zero
// ============================================================================
struct CvJobs {
    const float* src[9];
    __nv_bfloat16* dst[9];
    int off[10];
    int K[9], Kp[9], modes[9], total[9];
};

__global__ void convert_all(CvJobs jobs)
{
    int bid = blockIdx.x;
    int ji = 0;
#pragma unroll
    for (int t = 1; t < 9; t++) ji += (bid >= jobs.off[t]);
    int i = (bid - jobs.off[ji]) * 256 + threadIdx.x;
    if (i >= jobs.total[ji]) return;
    const float* src = jobs.src[ji];
    int K = jobs.K[ji], Kp = jobs.Kp[ji], modes = jobs.modes[ji];

    int Kt  = (Kp == 32) ? 128 : (Kp == 512 ? 1536 : 3072);
    int row = i / Kt;
    int rem = i - row * Kt;
    int seg = rem / Kp;
    int kk  = rem - seg * Kp;
    int mode = (modes >> (2 * seg)) & 3;
    float v = (mode != 2 && kk < K) ? src[(size_t)row * K + kk] : 0.f;
    __nv_bfloat16 h = __float2bfloat16(v);
    __nv_bfloat16 o = h;
    if (mode == 1) o = __float2bfloat16(v - __bfloat162float(h));
    jobs.dst[ji][i] = o;
}

// ============================================================================
// remaining small kernels
// ============================================================================
// Layer-1 backward: output at original t=T-1 is the FIRST reversed step (h0=0).
__global__ void gate_l1b_last(const float* __restrict__ bhh)
{
    const int idx = blockIdx.x * blockDim.x + threadIdx.x;
    const int b = idx >> 9;
    const int j = idx & 511;
    const float* gx = g_gx1b + (size_t)b * Gg;
    float r = sigmoidf_(gx[j] + bhh[j]);
    float z = sigmoidf_(gx[Hh + j] + bhh[Hh + j]);
    float n = tanhf(gx[2 * Hh + j] + r * bhh[2 * Hh + j]);
    g_h1b[(size_t)b * Hh + j] = (1.f - z) * n;
}

__global__ void concat_last(void)
{
    const int idx = blockIdx.x * blockDim.x + threadIdx.x;  // B*2H
    const int b = idx >> 10;
    const int j = idx & 1023;
    float v = (j < Hh) ? g_h1[(size_t)b * Hh + j] : g_h1b[(size_t)b * Hh + (j - Hh)];
    __nv_bfloat16 hh, hl;
    split_bf16(v, hh, hl);
    g_lasth[(size_t)b * H2 + j] = hh;
    g_lastl[(size_t)b * H2 + j] = hl;
}

// BN + ReLU + fc2 + log_softmax
__global__ void head_kernel(const float* __restrict__ gamma, const float* __restrict__ beta,
                            const float* __restrict__ mean, const float* __restrict__ var,
                            const float* __restrict__ fc2w, const float* __restrict__ fc2b,
                            float* __restrict__ out)
{
    const int b = blockIdx.x;
    const int tid = threadIdx.x;
    __shared__ float a[256];
    __shared__ float logits[10];

    float v = g_z1[(size_t)b * 256 + tid];
    v = (v - mean[tid]) * rsqrtf(var[tid] + 1e-5f) * gamma[tid] + beta[tid];
    a[tid] = fmaxf(v, 0.f);
    __syncthreads();

    if (tid < 10) {
        float acc = fc2b[tid];
        const float* wrow = fc2w + tid * 256;
        for (int k = 0; k < 256; k++) acc = fmaf(a[k], wrow[k], acc);
        logits[tid] = acc;
    }
    __syncthreads();

    if (tid == 0) {
        float mx = logits[0];
        for (int i = 1; i < 10; i++) mx = fmaxf(mx, logits[i]);
        float s = 0.f;
        for (int i = 0; i < 10; i++) s += expf(logits[i] - mx);
        float lse = mx + logf(s);
        for (int i = 0; i < 10; i++) out[(size_t)b * 10 + i] = logits[i] - lse;
    }
}

// ============================================================================
// host-side launch
// ============================================================================
extern "C" void kernel_launch(void* const* d_in, const int* in_sizes, int n_in,
                              void* d_out, int out_size)
{
    (void)in_sizes; (void)n_in; (void)out_size;
    const float* x         = (const float*)d_in[0];
    const float* W_ih_l0   = (const float*)d_in[1];
    const float* W_hh_l0   = (const float*)d_in[2];
    const float* b_ih_l0   = (const float*)d_in[3];
    const float* b_hh_l0   = (const float*)d_in[4];
    const float* W_ih_l0r  = (const float*)d_in[5];
    const float* W_hh_l0r  = (const float*)d_in[6];
    const float* b_ih_l0r  = (const float*)d_in[7];
    const float* b_hh_l0r  = (const float*)d_in[8];
    const float* W_ih_l1   = (const float*)d_in[9];
    const float* W_hh_l1   = (const float*)d_in[10];
    const float* b_ih_l1   = (const float*)d_in[11];
    const float* b_hh_l1   = (const float*)d_in[12];
    const float* W_ih_l1r  = (const float*)d_in[13];
    const float* W_hh_l1r  = (const float*)d_in[14];
    const float* b_ih_l1r  = (const float*)d_in[15];
    const float* b_hh_l1r  = (const float*)d_in[16];
    const float* fc1_w     = (const float*)d_in[17];
    const float* fc1_b     = (const float*)d_in[18];
    const float* bn_gamma  = (const float*)d_in[19];
    const float* bn_beta   = (const float*)d_in[20];
    const float* bn_mean   = (const float*)d_in[21];
    const float* bn_var    = (const float*)d_in[22];
    const float* fc2_w     = (const float*)d_in[23];
    const float* fc2_b     = (const float*)d_in[24];
    float* out = (float*)d_out;

    float *p_gxA, *p_gxB, *p_gx1b, *p_z1;
    __nv_bfloat16 *p_xs, *p_ws, *p_y0h, *p_y0l, *p_hh, *p_hl, *p_h1h, *p_h1l, *p_lh, *p_ll;
    cudaGetSymbolAddress((void**)&p_gxA,  g_gxA);
    cudaGetSymbolAddress((void**)&p_gxB,  g_gxB);
    cudaGetSymbolAddress((void**)&p_gx1b, g_gx1b);
    cudaGetSymbolAddress((void**)&p_z1,   g_z1);
    cudaGetSymbolAddress((void**)&p_xs,   g_xs);
    cudaGetSymbolAddress((void**)&p_ws,   g_ws);
    cudaGetSymbolAddress((void**)&p_y0h,  g_y0h);
    cudaGetSymbolAddress((void**)&p_y0l,  g_y0l);
    cudaGetSymbolAddress((void**)&p_hh,   g_hh);
    cudaGetSymbolAddress((void**)&p_hl,   g_hl);
    cudaGetSymbolAddress((void**)&p_h1h,  g_h1h);
    cudaGetSymbolAddress((void**)&p_h1l,  g_h1l);
    cudaGetSymbolAddress((void**)&p_lh,   g_lasth);
    cudaGetSymbolAddress((void**)&p_ll,   g_lastl);

    float *p_h, *p_h1;
    cudaGetSymbolAddress((void**)&p_h,  g_h);
    cudaGetSymbolAddress((void**)&p_h1, g_h1);

    cudaFuncSetAttribute(mma_gemm,  cudaFuncAttributeMaxDynamicSharedMemorySize, SMEM_SZ);
    cudaFuncSetAttribute(rec3_step, cudaFuncAttributeMaxDynamicSharedMemorySize, R3_SMEM);

    // seg-mode packs: 0=hi, 1=lo, 2=zero (2 bits per segment)
    const int MODES_A4 = 0 | (0 << 2) | (1 << 4) | (2 << 6);  // [hi|hi|lo|0]
    const int MODES_W4 = 0 | (1 << 2) | (0 << 4) | (2 << 6);  // [hi|lo|hi|0]
    const int MODES_W3 = 0 | (1 << 2) | (0 << 4);             // [hi|lo|hi]

    // 0) conversions (one launch) + zero init (one launch)
    {
        CvJobs cj;
        const float* srcs[9] = { x, W_ih_l0, W_ih_l0r, W_hh_l0, W_hh_l0r,
                                 W_hh_l1, W_ih_l1, W_ih_l1r, fc1_w };
        __nv_bfloat16* dsts[9] = { p_xs, p_ws + WS_IH_L0, p_ws + WS_IH_L0R,
                                   p_ws + WS_HH_L0, p_ws + WS_HH_L0R, p_ws + WS_HH_L1,
                                   p_ws + WS_IH_L1, p_ws + WS_IH_L1R, p_ws + WS_FC1 };
        int Ks[9]  = { 28, 28, 28, 512, 512, 512, 1024, 1024, 1024 };
        int Kps[9] = { 32, 32, 32, 512, 512, 512, 1024, 1024, 1024 };
        int mds[9] = { MODES_A4, MODES_W4, MODES_W4, MODES_W3, MODES_W3,
                       MODES_W3, MODES_W3, MODES_W3, MODES_W3 };
        int tots[9] = { MT * 128, 1536 * 128, 1536 * 128, 1536 * 1536, 1536 * 1536,
                        1536 * 1536, 1536 * 3072, 1536 * 3072, 256 * 3072 };
        int off = 0;
        for (int i = 0; i < 9; i++) {
            cj.src[i] = srcs[i]; cj.dst[i] = dsts[i];
            cj.K[i] = Ks[i]; cj.Kp[i] = Kps[i]; cj.modes[i] = mds[i]; cj.total[i] = tots[i];
            cj.off[i] = off;
            off += (tots[i] + 255) / 256;
        }
        cj.off[9] = off;
        convert_all<<<off, 256>>>(cj);
        zero_all<<<(ZTOT + 255) / 256, 256>>>();
    }

    // 1) layer-0 input projections (fwd+bwd), physical stacked xs, K'=128
    {
        MOp f{ p_xs, p_xs, p_ws + WS_IH_L0,  b_ih_l0,  p_gxA, 128, 0 };
        MOp r{ p_xs, p_xs, p_ws + WS_IH_L0R, b_ih_l0r, p_gxB, 128, 0 };
        mma_gemm<<<dim3(Gg / 128, MT / 128, 2), 256, SMEM_SZ>>>(f, r, 128, Gg, 128, 30);
    }

    // 2) layer-0 recurrence: gate-fused rec3 (natural layout), fwd+bwd per launch
    for (int s = 0; s < Tt; s++) {
        const int cur = s & 1;
        const size_t ib = (size_t)cur * 2 * BH;
        const size_t ob = (size_t)(cur ^ 1) * 2 * BH;
        R3Op f{ p_hh + ib,      p_hl + ib,      p_ws + WS_HH_L0,  b_hh_l0,  p_gxA,
                p_h,      p_hh + ob,      p_hl + ob,      p_y0h, p_y0l, s, 0 };
        R3Op r{ p_hh + ib + BH, p_hl + ib + BH, p_ws + WS_HH_L0R, b_hh_l0r, p_gxB,
                p_h + BH, p_hh + ob + BH, p_hl + ob + BH, p_y0h, p_y0l, Tt - 1 - s, 512 };
        rec3_step<<<dim3(4, Bv / 128, 2), 256, R3_SMEM>>>(f, r);
    }

    // 3) layer-1 input projection (fwd, all t), virtual y0 [hi|hi|lo], K'=3072
    {
        MOp f{ p_y0h, p_y0l, p_ws + WS_IH_L1, b_ih_l1, p_gxA, 1024, 0 };
        mma_gemm<<<dim3(Gg / 128, MT / 128, 1), 256, SMEM_SZ>>>(f, f, 3072, Gg, 3072, 10);
    }

    // 4) layer-1 bwd input projection at t=T-1 only
    {
        MOp f{ p_y0h + (size_t)(Tt - 1) * 1024, p_y0l + (size_t)(Tt - 1) * 1024,
               p_ws + WS_IH_L1R, b_ih_l1r, p_gx1b, Tt * 1024, 0 };
        mma_gemm<<<dim3(Gg / 128, Bv / 128, 1), 256, SMEM_SZ>>>(f, f, 3072, Gg, 3072, 10);
    }
    gate_l1b_last<<<BH / 256, 256>>>(b_hh_l1r);

    // 5) layer-1 fwd recurrence: gate-fused rec3, single wave (128 CTAs)
    for (int s = 0; s < Tt; s++) {
        const int cur = s & 1;
        R3Op f{ p_h1h + (size_t)cur * BH, p_h1l + (size_t)cur * BH,
                p_ws + WS_HH_L1, b_hh_l1, p_gxA, p_h1,
                p_h1h + (size_t)(cur ^ 1) * BH, p_h1l + (size_t)(cur ^ 1) * BH,
                nullptr, nullptr, s, 0 };
        rec3_step<<<dim3(4, Bv / 128, 1), 256, R3_SMEM>>>(f, f);
    }

    // 6) head
    concat_last<<<(Bv * H2) / 256, 256>>>();
    {
        MOp f{ p_lh, p_ll, p_ws + WS_FC1, fc1_b, p_z1, 1024, 0 };
        mma_gemm<<<dim3(256 / 128, Bv / 128, 1), 256, SMEM_SZ>>>(f, f, 3072, 256, 3072, 10);
    }
    head_kernel<<<Bv, 256>>>(bn_gamma, bn_beta, bn_mean, bn_var, fc2_w, fc2_b, out);
}

// round 16
// speedup vs baseline: 1.7278x; 1.7278x over previous
#include <cuda_runtime.h>
#include <cuda_bf16.h>
#include <math.h>
#include <stdint.h>

// Problem dims
#define Bv 4096
#define Tt 28
#define In 28
#define Hh 512
#define Gg 1536   // 3*H
#define H2 1024   // 2*H

#define BH 2097152      // B*H
#define BG 6291456      // B*3H
#define MT 114688       // B*T

// ---------------- scratch (static device allocations; allowed) ----------------
__device__ float g_gxA[176160768];   // B*T*3H : gx layer0 fwd, reused as gx layer1 fwd
__device__ float g_gxB[176160768];   // B*T*3H : gx layer0 bwd
__device__ float g_gh[2 * 6291456];  // L0: [dir][B,1536]; L1: [gh | gh2] split-K halves
__device__ float g_h[2 * 2097152];   // layer0 fwd/bwd hidden (fp32 state)
__device__ float g_h1[2097152];      // layer1 fwd hidden (fp32 state)
__device__ float g_h1b[2097152];     // layer1 bwd hidden (one step)
__device__ float g_gx1b[6291456];    // layer1 bwd gx at t=T-1
__device__ float g_z1[1048576];      // B*256 fc1 output
__device__ float g_zb[1536];         // zero bias

// bf16 operands. A-side stores hi+lo only; GEMMs synthesize [hi|hi|lo] virtually.
// W-side physically stacked [Wh|Wl|Wh].
// L0 hidden state lives DIRECTLY in y0 (y0[b,t,dir*512+j] == h_dir(t)[b,j]) —
// the recurrent GEMM reads it strided (lda = T*1024); no separate mirrors.
__device__ __nv_bfloat16 g_xs[14680064];     // x stacked [B*T,128] physical [hi|hi|lo|0]
__device__ __nv_bfloat16 g_ws[17694720];     // weights arena (stacked)
__device__ __nv_bfloat16 g_y0h[117440512];   // y0 hi [B*T,1024] (= L0 h state history)
__device__ __nv_bfloat16 g_y0l[117440512];   // y0 lo [B*T,1024]
__device__ __nv_bfloat16 g_z0h[2097152];     // zero initial state hi [B,512]
__device__ __nv_bfloat16 g_z0l[2097152];     // zero initial state lo [B,512]
__device__ __nv_bfloat16 g_h1h[2*2097152];   // l1 h hi, [buf][B,512]
__device__ __nv_bfloat16 g_h1l[2*2097152];   // l1 h lo
__device__ __nv_bfloat16 g_lasth[4194304];   // concat hi [B,1024]
__device__ __nv_bfloat16 g_lastl[4194304];   // concat lo [B,1024]

// Weight arena offsets (bf16 elements)
#define WS_IH_L0   0          // 1536 x 128
#define WS_IH_L0R  196608
#define WS_HH_L0   393216     // 1536 x 1536
#define WS_HH_L0R  2752512
#define WS_HH_L1   5111808
#define WS_IH_L1   7471104    // 1536 x 3072
#define WS_IH_L1R  12189696
#define WS_FC1     16908288   // 256 x 3072

// ============================================================================
// PTX helpers (baseline sm_80+ features; valid on .target sm_103)
// ============================================================================
__device__ __forceinline__ uint32_t smem_u32(const void* p) {
    uint32_t a;
    asm("{ .reg .u64 t; cvta.to.shared.u64 t, %1; cvt.u32.u64 %0, t; }" : "=r"(a) : "l"(p));
    return a;
}
__device__ __forceinline__ void cp16(uint32_t s, const void* g) {
    asm volatile("cp.async.cg.shared.global [%0], [%1], 16;" :: "r"(s), "l"(g));
}
__device__ __forceinline__ void ldsm4(uint32_t* r, uint32_t a) {
    asm volatile("ldmatrix.sync.aligned.m8n8.x4.shared.b16 {%0,%1,%2,%3}, [%4];"
                 : "=r"(r[0]), "=r"(r[1]), "=r"(r[2]), "=r"(r[3]) : "r"(a));
}
__device__ __forceinline__ void mma16816(float* d, const uint32_t* a, uint32_t b0, uint32_t b1) {
    asm volatile("mma.sync.aligned.m16n8k16.row.col.f32.bf16.bf16.f32 "
                 "{%0,%1,%2,%3}, {%4,%5,%6,%7}, {%8,%9}, {%0,%1,%2,%3};"
                 : "+f"(d[0]), "+f"(d[1]), "+f"(d[2]), "+f"(d[3])
                 : "r"(a[0]), "r"(a[1]), "r"(a[2]), "r"(a[3]), "r"(b0), "r"(b1));
}

__device__ __forceinline__ float sigmoidf_(float x) { return 1.f / (1.f + expf(-x)); }
__device__ __forceinline__ void split_bf16(float v, __nv_bfloat16& h, __nv_bfloat16& l) {
    h = __float2bfloat16(v);
    l = __float2bfloat16(v - __bfloat162float(h));
}

// ============================================================================
// Pipelined bf16 GEMM: C = A' @ W'^T + bias (fp32 accum), virtual-stacked A.
// A' column k maps to: seg = k>>kshift; seg<2 -> Ahi[k & mask], seg2 -> Alo.
// (physical A: kshift=30 so seg==0 always and k indexes Ahi directly)
// W: [N, ldw] physically stacked, offset by koff via pre-offset pointer.
// 128x128x64 tiles, 3-stage cp.async, swizzled ldmatrix, 8 warps (64x32 each).
// (R10-proven shape — do not disturb.)
// ============================================================================
struct MOp {
    const __nv_bfloat16 *Ahi, *Alo;  // hi / lo A arrays (row stride lda each)
    const __nv_bfloat16 *W;          // stacked weights (pre-offset for split-K)
    const float *bias;
    float *C;
    int lda;
    int koff;                        // split-K offset into virtual A columns
};

#define STAGE_B 32768               // A tile 16KB + W tile 16KB
#define SMEM_SZ (3 * STAGE_B)       // 98304

__device__ __forceinline__ void prefetch_stage(const MOp& op, uint32_t sb, int c,
                                               int bm, int bn, int ldw,
                                               int kshift, int kmask, int tid)
{
    const int st = c % 3;
    const uint32_t abase = sb + st * STAGE_B;
    const uint32_t wbase = abase + 16384;
    const int kc0 = c * 64;
#pragma unroll
    for (int i = 0; i < 4; i++) {
        int v = tid + i * 256;          // 0..1023
        int row = v >> 3, ch = v & 7;   // 128 rows x 8 chunks(16B)
        int kg  = op.koff + kc0 + ch * 8;
        int seg = kg >> kshift;
        int off = kg & kmask;
        const __nv_bfloat16* g = (seg < 2 ? op.Ahi : op.Alo)
                               + (size_t)(bm + row) * op.lda + off;
        cp16(abase + row * 128 + ((ch ^ (row & 7)) << 4), g);
    }
#pragma unroll
    for (int i = 0; i < 4; i++) {
        int v = tid + i * 256;
        int row = v >> 3, ch = v & 7;
        const __nv_bfloat16* g = op.W + (size_t)(bn + row) * ldw + kc0 + ch * 8;
        cp16(wbase + row * 128 + ((ch ^ (row & 7)) << 4), g);
    }
    asm volatile("cp.async.commit_group;");
}

__global__ void __launch_bounds__(256, 2) mma_gemm(MOp op0, MOp op1,
                                                   int ldw, int ldc, int K, int kshift)
{
    extern __shared__ char smem[];
    MOp op = (blockIdx.z == 0) ? op0 : op1;
    const uint32_t sb = smem_u32(smem);
    const int kmask = (kshift >= 30) ? 0x3FFFFFFF : ((1 << kshift) - 1);
    const int tid  = threadIdx.x;
    const int wid  = tid >> 5;
    const int lane = tid & 31;
    const int bm = blockIdx.y * 128;
    const int bn = blockIdx.x * 128;
    const int wm = (wid >> 2) * 64;   // 2 warp rows
    const int wn = (wid & 3) * 32;    // 4 warp cols

    float acc[4][4][4];
#pragma unroll
    for (int i = 0; i < 4; i++)
#pragma unroll
        for (int j = 0; j < 4; j++)
#pragma unroll
            for (int r = 0; r < 4; r++) acc[i][j][r] = 0.f;

    const int nc = K >> 6;

    prefetch_stage(op, sb, 0, bm, bn, ldw, kshift, kmask, tid);
    if (nc > 1) prefetch_stage(op, sb, 1, bm, bn, ldw, kshift, kmask, tid);

    for (int c = 0; c < nc; c++) {
        if (c + 2 < nc) {
            prefetch_stage(op, sb, c + 2, bm, bn, ldw, kshift, kmask, tid);
            asm volatile("cp.async.wait_group 2;");
        } else if (c + 1 < nc) {
            asm volatile("cp.async.wait_group 1;");
        } else {
            asm volatile("cp.async.wait_group 0;");
        }
        __syncthreads();

        const int st = c % 3;
        const uint32_t abase = sb + st * STAGE_B;
        const uint32_t wbase = abase + 16384;

#pragma unroll
        for (int kk = 0; kk < 4; kk++) {   // K=16 steps within BK=64
            uint32_t a[4][4], b[2][4];
#pragma unroll
            for (int mf = 0; mf < 4; mf++) {
                int r   = wm + mf * 16 + ((lane >> 3) & 1) * 8 + (lane & 7);
                int cch = kk * 2 + (lane >> 4);
                ldsm4(a[mf], abase + r * 128 + ((cch ^ (r & 7)) << 4));
            }
#pragma unroll
            for (int nf = 0; nf < 2; nf++) {
                int r   = wn + nf * 16 + ((lane >> 4) & 1) * 8 + (lane & 7);
                int cch = kk * 2 + ((lane >> 3) & 1);
                ldsm4(b[nf], wbase + r * 128 + ((cch ^ (r & 7)) << 4));
            }
#pragma unroll
            for (int mf = 0; mf < 4; mf++)
#pragma unroll
                for (int nt = 0; nt < 4; nt++)
                    mma16816(acc[mf][nt], a[mf],
                             b[nt >> 1][(nt & 1) * 2], b[nt >> 1][(nt & 1) * 2 + 1]);
        }
        __syncthreads();
    }

    // epilogue: bias + fp32 store
#pragma unroll
    for (int mf = 0; mf < 4; mf++) {
        int row = bm + wm + mf * 16 + (lane >> 2);
#pragma unroll
        for (int nt = 0; nt < 4; nt++) {
            int col = bn + wn + nt * 8 + (lane & 3) * 2;
            float b0 = op.bias[col], b1 = op.bias[col + 1];
            float2 v0 = make_float2(acc[mf][nt][0] + b0, acc[mf][nt][1] + b1);
            float2 v1 = make_float2(acc[mf][nt][2] + b0, acc[mf][nt][3] + b1);
            *(float2*)(op.C + (size_t)row * ldc + col) = v0;
            *(float2*)(op.C + (size_t)(row + 8) * ldc + col) = v1;
        }
    }
}

// ============================================================================
// init: zero all state in one launch
// f32: g_h (2BH), g_h1 (BH), g_zb (1536)
// bf16: g_z0h (BH), g_z0l (BH), g_h1h buf0 (BH), g_h1l buf0 (BH)
// ============================================================================
#define ZF1 (2 * BH)
#define ZF2 (ZF1 + BH)
#define ZF3 (ZF2 + 1536)
#define ZB1 (BH)
#define ZB2 (ZB1 + BH)
#define ZB3 (ZB2 + BH)
#define ZB4 (ZB3 + BH)
#define ZTOT (ZF3 + ZB4)

__global__ void zero_all(void)
{
    long long i = (long long)blockIdx.x * blockDim.x + threadIdx.x;
    if (i >= ZTOT) return;
    if (i < ZF3) {
        if (i < ZF1)      g_h[i] = 0.f;
        else if (i < ZF2) g_h1[i - ZF1] = 0.f;
        else              g_zb[i - ZF2] = 0.f;
    } else {
        long long k = i - ZF3;
        __nv_bfloat16 z = __float2bfloat16(0.f);
        if (k < ZB1)      g_z0h[k] = z;
        else if (k < ZB2) g_z0l[k - ZB1] = z;
        else if (k < ZB3) g_h1h[k - ZB2] = z;
        else              g_h1l[k - ZB3] = z;
    }
}

// ============================================================================
// conversion: all hi/lo stacking jobs in one launch (block-offset job table)
// per-seg mode: 0=hi, 1=lo, 2=zero
// ============================================================================
struct CvJobs {
    const float* src[9];
    __nv_bfloat16* dst[9];
    int off[10];          // cumulative block offsets
    int K[9], Kp[9], modes[9], total[9];
};

__global__ void convert_all(CvJobs jobs)
{
    int bid = blockIdx.x;
    int ji = 0;
#pragma unroll
    for (int t = 1; t < 9; t++) ji += (bid >= jobs.off[t]);
    int i = (bid - jobs.off[ji]) * 256 + threadIdx.x;
    if (i >= jobs.total[ji]) return;
    const float* src = jobs.src[ji];
    int K = jobs.K[ji], Kp = jobs.Kp[ji], modes = jobs.modes[ji];

    int Kt  = (Kp == 32) ? 128 : (Kp == 512 ? 1536 : 3072);
    int row = i / Kt;
    int rem = i - row * Kt;
    int seg = rem / Kp;
    int kk  = rem - seg * Kp;
    int mode = (modes >> (2 * seg)) & 3;
    float v = (mode != 2 && kk < K) ? src[(size_t)row * K + kk] : 0.f;
    __nv_bfloat16 h = __float2bfloat16(v);
    __nv_bfloat16 o = h;
    if (mode == 1) o = __float2bfloat16(v - __bfloat162float(h));
    jobs.dst[ji][i] = o;
}

// ============================================================================
// gate kernels
// ============================================================================
// Layer-0 gating, both directions (blockIdx.y = dir). fp32 state + y0 write
// (y0 doubles as the bf16 hidden-state history read by the next step's GEMM).
__global__ void gru_gate_l0(int s)
{
    const int idx = blockIdx.x * blockDim.x + threadIdx.x;  // over B*H
    const int dir = blockIdx.y;
    const int b = idx >> 9;
    const int j = idx & 511;
    const int t = (dir == 0) ? s : (Tt - 1 - s);

    const float* gx = (dir == 0 ? g_gxA : g_gxB) + ((size_t)b * Tt + t) * Gg;
    const float* gh = g_gh + (size_t)dir * BG + (size_t)b * Gg;
    const size_t hidx = (size_t)dir * BH + (size_t)b * Hh + j;

    float r = sigmoidf_(gx[j] + gh[j]);
    float z = sigmoidf_(gx[Hh + j] + gh[Hh + j]);
    float n = tanhf(gx[2 * Hh + j] + r * gh[2 * Hh + j]);
    float hn = (1.f - z) * n + z * g_h[hidx];
    g_h[hidx] = hn;

    __nv_bfloat16 hh, hl;
    split_bf16(hn, hh, hl);
    const size_t yi = ((size_t)b * Tt + t) * 1024 + (size_t)dir * Hh + j;
    g_y0h[yi] = hh; g_y0l[yi] = hl;
}

// Layer-1 gating: gh comes in two split-K halves summed here.
__global__ void gru_gate_l1(int s, int cur)
{
    const int idx = blockIdx.x * blockDim.x + threadIdx.x;
    const int b = idx >> 9;
    const int j = idx & 511;

    const float* gx  = g_gxA + ((size_t)b * Tt + s) * Gg;
    const float* gh  = g_gh + (size_t)b * Gg;
    const float* gh2 = g_gh + (size_t)BG + (size_t)b * Gg;
    const size_t hidx = (size_t)b * Hh + j;

    float ar = gh[j] + gh2[j];
    float az = gh[Hh + j] + gh2[Hh + j];
    float an = gh[2 * Hh + j] + gh2[2 * Hh + j];
    float r = sigmoidf_(gx[j] + ar);
    float z = sigmoidf_(gx[Hh + j] + az);
    float n = tanhf(gx[2 * Hh + j] + r * an);
    float hn = (1.f - z) * n + z * g_h1[hidx];
    g_h1[hidx] = hn;

    __nv_bfloat16 hh, hl;
    split_bf16(hn, hh, hl);
    const size_t mo = (size_t)(cur ^ 1) * BH + hidx;
    g_h1h[mo] = hh;  g_h1l[mo] = hl;
}

// Layer-1 backward: output at original t=T-1 is the FIRST reversed step (h0=0).
__global__ void gate_l1b_last(const float* __restrict__ bhh)
{
    const int idx = blockIdx.x * blockDim.x + threadIdx.x;
    const int b = idx >> 9;
    const int j = idx & 511;
    const float* gx = g_gx1b + (size_t)b * Gg;
    float r = sigmoidf_(gx[j] + bhh[j]);
    float z = sigmoidf_(gx[Hh + j] + bhh[Hh + j]);
    float n = tanhf(gx[2 * Hh + j] + r * bhh[2 * Hh + j]);
    g_h1b[(size_t)b * Hh + j] = (1.f - z) * n;
}

__global__ void concat_last(void)
{
    const int idx = blockIdx.x * blockDim.x + threadIdx.x;  // B*2H
    const int b = idx >> 10;
    const int j = idx & 1023;
    float v = (j < Hh) ? g_h1[(size_t)b * Hh + j] : g_h1b[(size_t)b * Hh + (j - Hh)];
    __nv_bfloat16 hh, hl;
    split_bf16(v, hh, hl);
    g_lasth[(size_t)b * H2 + j] = hh;
    g_lastl[(size_t)b * H2 + j] = hl;
}

// BN + ReLU + fc2 + log_softmax
__global__ void head_kernel(const float* __restrict__ gamma, const float* __restrict__ beta,
                            const float* __restrict__ mean, const float* __restrict__ var,
                            const float* __restrict__ fc2w, const float* __restrict__ fc2b,
                            float* __restrict__ out)
{
    const int b = blockIdx.x;
    const int tid = threadIdx.x;
    __shared__ float a[256];
    __shared__ float logits[10];

    float v = g_z1[(size_t)b * 256 + tid];
    v = (v - mean[tid]) * rsqrtf(var[tid] + 1e-5f) * gamma[tid] + beta[tid];
    a[tid] = fmaxf(v, 0.f);
    __syncthreads();

    if (tid < 10) {
        float acc = fc2b[tid];
        const float* wrow = fc2w + tid * 256;
        for (int k = 0; k < 256; k++) acc = fmaf(a[k], wrow[k], acc);
        logits[tid] = acc;
    }
    __syncthreads();

    if (tid == 0) {
        float mx = logits[0];
        for (int i = 1; i < 10; i++) mx = fmaxf(mx, logits[i]);
        float s = 0.f;
        for (int i = 0; i < 10; i++) s += expf(logits[i] - mx);
        float lse = mx + logf(s);
        for (int i = 0; i < 10; i++) out[(size_t)b * 10 + i] = logits[i] - lse;
    }
}

// ============================================================================
// host-side launch
// ============================================================================
extern "C" void kernel_launch(void* const* d_in, const int* in_sizes, int n_in,
                              void* d_out, int out_size)
{
    (void)in_sizes; (void)n_in; (void)out_size;
    const float* x         = (const float*)d_in[0];
    const float* W_ih_l0   = (const float*)d_in[1];
    const float* W_hh_l0   = (const float*)d_in[2];
    const float* b_ih_l0   = (const float*)d_in[3];
    const float* b_hh_l0   = (const float*)d_in[4];
    const float* W_ih_l0r  = (const float*)d_in[5];
    const float* W_hh_l0r  = (const float*)d_in[6];
    const float* b_ih_l0r  = (const float*)d_in[7];
    const float* b_hh_l0r  = (const float*)d_in[8];
    const float* W_ih_l1   = (const float*)d_in[9];
    const float* W_hh_l1   = (const float*)d_in[10];
    const float* b_ih_l1   = (const float*)d_in[11];
    const float* b_hh_l1   = (const float*)d_in[12];
    const float* W_ih_l1r  = (const float*)d_in[13];
    const float* W_hh_l1r  = (const float*)d_in[14];
    const float* b_ih_l1r  = (const float*)d_in[15];
    const float* b_hh_l1r  = (const float*)d_in[16];
    const float* fc1_w     = (const float*)d_in[17];
    const float* fc1_b     = (const float*)d_in[18];
    const float* bn_gamma  = (const float*)d_in[19];
    const float* bn_beta   = (const float*)d_in[20];
    const float* bn_mean   = (const float*)d_in[21];
    const float* bn_var    = (const float*)d_in[22];
    const float* fc2_w     = (const float*)d_in[23];
    const float* fc2_b     = (const float*)d_in[24];
    float* out = (float*)d_out;

    float *p_gxA, *p_gxB, *p_gh, *p_gx1b, *p_z1, *p_zb;
    __nv_bfloat16 *p_xs, *p_ws, *p_y0h, *p_y0l, *p_z0h, *p_z0l, *p_h1h, *p_h1l, *p_lh, *p_ll;
    cudaGetSymbolAddress((void**)&p_gxA,  g_gxA);
    cudaGetSymbolAddress((void**)&p_gxB,  g_gxB);
    cudaGetSymbolAddress((void**)&p_gh,   g_gh);
    cudaGetSymbolAddress((void**)&p_gx1b, g_gx1b);
    cudaGetSymbolAddress((void**)&p_z1,   g_z1);
    cudaGetSymbolAddress((void**)&p_zb,   g_zb);
    cudaGetSymbolAddress((void**)&p_xs,   g_xs);
    cudaGetSymbolAddress((void**)&p_ws,   g_ws);
    cudaGetSymbolAddress((void**)&p_y0h,  g_y0h);
    cudaGetSymbolAddress((void**)&p_y0l,  g_y0l);
    cudaGetSymbolAddress((void**)&p_z0h,  g_z0h);
    cudaGetSymbolAddress((void**)&p_z0l,  g_z0l);
    cudaGetSymbolAddress((void**)&p_h1h,  g_h1h);
    cudaGetSymbolAddress((void**)&p_h1l,  g_h1l);
    cudaGetSymbolAddress((void**)&p_lh,   g_lasth);
    cudaGetSymbolAddress((void**)&p_ll,   g_lastl);

    cudaFuncSetAttribute(mma_gemm, cudaFuncAttributeMaxDynamicSharedMemorySize, SMEM_SZ);

    // seg-mode packs: 0=hi, 1=lo, 2=zero (2 bits per segment)
    const int MODES_A4 = 0 | (0 << 2) | (1 << 4) | (2 << 6);  // [hi|hi|lo|0]
    const int MODES_W4 = 0 | (1 << 2) | (0 << 4) | (2 << 6);  // [hi|lo|hi|0]
    const int MODES_W3 = 0 | (1 << 2) | (0 << 4);             // [hi|lo|hi]

    // 0) conversions (one launch) + zero init (one launch)
    {
        CvJobs cj;
        const float* srcs[9] = { x, W_ih_l0, W_ih_l0r, W_hh_l0, W_hh_l0r,
                                 W_hh_l1, W_ih_l1, W_ih_l1r, fc1_w };
        __nv_bfloat16* dsts[9] = { p_xs, p_ws + WS_IH_L0, p_ws + WS_IH_L0R,
                                   p_ws + WS_HH_L0, p_ws + WS_HH_L0R, p_ws + WS_HH_L1,
                                   p_ws + WS_IH_L1, p_ws + WS_IH_L1R, p_ws + WS_FC1 };
        int Ks[9]  = { 28, 28, 28, 512, 512, 512, 1024, 1024, 1024 };
        int Kps[9] = { 32, 32, 32, 512, 512, 512, 1024, 1024, 1024 };
        int mds[9] = { MODES_A4, MODES_W4, MODES_W4, MODES_W3, MODES_W3,
                       MODES_W3, MODES_W3, MODES_W3, MODES_W3 };
        int tots[9] = { MT * 128, 1536 * 128, 1536 * 128, 1536 * 1536, 1536 * 1536,
                        1536 * 1536, 1536 * 3072, 1536 * 3072, 256 * 3072 };
        int off = 0;
        for (int i = 0; i < 9; i++) {
            cj.src[i] = srcs[i]; cj.dst[i] = dsts[i];
            cj.K[i] = Ks[i]; cj.Kp[i] = Kps[i]; cj.modes[i] = mds[i]; cj.total[i] = tots[i];
            cj.off[i] = off;
            off += (tots[i] + 255) / 256;
        }
        cj.off[9] = off;
        convert_all<<<off, 256>>>(cj);
        zero_all<<<(ZTOT + 255) / 256, 256>>>();
    }

    // 1) layer-0 input projections (fwd+bwd), physical stacked xs, K'=128
    {
        MOp f{ p_xs, p_xs, p_ws + WS_IH_L0,  b_ih_l0,  p_gxA, 128, 0 };
        MOp r{ p_xs, p_xs, p_ws + WS_IH_L0R, b_ih_l0r, p_gxB, 128, 0 };
        mma_gemm<<<dim3(Gg / 128, MT / 128, 2), 256, SMEM_SZ>>>(f, r, 128, Gg, 128, 30);
    }

    // 2) layer-0 recurrence: GEMM reads h state from y0 (strided) or the zero
    //    buffer at s=0; gate writes only into y0 at the step's time slot.
    for (int s = 0; s < Tt; s++) {
        MOp f, r;
        if (s == 0) {
            f = MOp{ p_z0h, p_z0l, p_ws + WS_HH_L0,  b_hh_l0,  p_gh,      512, 0 };
            r = MOp{ p_z0h, p_z0l, p_ws + WS_HH_L0R, b_hh_l0r, p_gh + BG, 512, 0 };
        } else {
            const int tf = s - 1;       // fwd state written at time s-1
            const int tb = Tt - s;      // bwd state written at time 28-s
            f = MOp{ p_y0h + (size_t)tf * 1024,       p_y0l + (size_t)tf * 1024,
                     p_ws + WS_HH_L0,  b_hh_l0,  p_gh,      Tt * 1024, 0 };
            r = MOp{ p_y0h + (size_t)tb * 1024 + 512, p_y0l + (size_t)tb * 1024 + 512,
                     p_ws + WS_HH_L0R, b_hh_l0r, p_gh + BG, Tt * 1024, 0 };
        }
        mma_gemm<<<dim3(Gg / 128, Bv / 128, 2), 256, SMEM_SZ>>>(f, r, Gg, Gg, Gg, 9);
        gru_gate_l0<<<dim3(BH / 256, 2), 256>>>(s);
    }

    // 3) layer-1 input projection (fwd, all t), virtual y0 [hi|hi|lo], K'=3072
    {
        MOp f{ p_y0h, p_y0l, p_ws + WS_IH_L1, b_ih_l1, p_gxA, 1024, 0 };
        mma_gemm<<<dim3(Gg / 128, MT / 128, 1), 256, SMEM_SZ>>>(f, f, 3072, Gg, 3072, 10);
    }

    // 4) layer-1 bwd input projection at t=T-1 only
    {
        MOp f{ p_y0h + (size_t)(Tt - 1) * 1024, p_y0l + (size_t)(Tt - 1) * 1024,
               p_ws + WS_IH_L1R, b_ih_l1r, p_gx1b, Tt * 1024, 0 };
        mma_gemm<<<dim3(Gg / 128, Bv / 128, 1), 256, SMEM_SZ>>>(f, f, 3072, Gg, 3072, 10);
    }
    gate_l1b_last<<<BH / 256, 256>>>(b_hh_l1r);

    // 5) layer-1 fwd recurrence: split-K (two 768-halves), double-buffered mirrors
    for (int s = 0; s < Tt; s++) {
        const int cur = s & 1;
        const size_t mb = (size_t)cur * BH;
        MOp h0{ p_h1h + mb, p_h1l + mb, p_ws + WS_HH_L1,       b_hh_l1, p_gh,      512, 0 };
        MOp h1{ p_h1h + mb, p_h1l + mb, p_ws + WS_HH_L1 + 768, p_zb,    p_gh + BG, 512, 768 };
        mma_gemm<<<dim3(Gg / 128, Bv / 128, 2), 256, SMEM_SZ>>>(h0, h1, Gg, Gg, 768, 9);
        gru_gate_l1<<<BH / 256, 256>>>(s, cur);
    }

    // 6) head
    concat_last<<<(Bv * H2) / 256, 256>>>();
    {
        MOp f{ p_lh, p_ll, p_ws + WS_FC1, fc1_b, p_z1, 1024, 0 };
        mma_gemm<<<dim3(256 / 128, Bv / 128, 1), 256, SMEM_SZ>>>(f, f, 3072, 256, 3072, 10);
    }
    head_kernel<<<Bv, 256>>>(bn_gamma, bn_beta, bn_mean, bn_var, fc2_w, fc2_b, out);
}

// round 17
// speedup vs baseline: 1.8825x; 1.0896x over previous
#include <cuda_runtime.h>
#include <cuda_bf16.h>
#include <cuda_fp16.h>
#include <math.h>
#include <stdint.h>

// Problem dims
#define Bv 4096
#define Tt 28
#define In 28
#define Hh 512
#define Gg 1536   // 3*H
#define H2 1024   // 2*H

#define BH 2097152      // B*H
#define BG 6291456      // B*3H
#define MT 114688       // B*T

// ---------------- scratch (static device allocations; allowed) ----------------
__device__ float g_gxA[176160768];   // B*T*3H : gx layer0 fwd, reused as gx layer1 fwd
__device__ float g_gxB[176160768];   // B*T*3H : gx layer0 bwd
__device__ float g_gh[2 * 6291456];  // L0: [dir][B,1536]; L1: [gh | gh2] split-K halves
__device__ float g_h[2 * 2097152];   // layer0 fwd/bwd hidden (fp32 state)
__device__ float g_h1[2097152];      // layer1 fwd hidden (fp32 state)
__device__ float g_h1b[2097152];     // layer1 bwd hidden (one step)
__device__ float g_gx1b[6291456];    // layer1 bwd gx at t=T-1
__device__ float g_z1[1048576];      // B*256 fc1 output
__device__ float g_zb[1536];         // zero bias

// bf16 operands (recurrence path, 3-term split: exact to ~2^-17)
__device__ __nv_bfloat16 g_xs[14680064];     // x stacked [B*T,128] physical [hi|hi|lo|0]
__device__ __nv_bfloat16 g_ws[7471104];      // bf16 weights arena — FIXED SIZE (R12 had
                                             // 5963776: W_hh_l1 overflowed by 2.9MB and
                                             // corrupted the L1 recurrence -> rel_err 0.118)
__device__ __nv_bfloat16 g_hh[2*2*2097152];  // l0 h hi, [buf][dir][B,512]
__device__ __nv_bfloat16 g_hl[2*2*2097152];  // l0 h lo
__device__ __nv_bfloat16 g_h1h[2*2097152];   // l1 h hi, [buf][B,512]
__device__ __nv_bfloat16 g_h1l[2*2097152];   // l1 h lo

// fp16 operands (input-projection path, 2-term: A exact hi/lo, W fp16-rounded)
__device__ __half g_y0h[117440512];          // y0 hi [B*T,1024]
__device__ __half g_y0l[117440512];          // y0 lo [B*T,1024]
__device__ __half g_lasth[4194304];          // concat hi [B,1024]
__device__ __half g_lastl[4194304];          // concat lo [B,1024]
__device__ __half g_wf[6815744];             // fp16 dup-weights arena

// bf16 arena offsets
#define WS_IH_L0   0          // 1536 x 128
#define WS_IH_L0R  196608
#define WS_HH_L0   393216     // 1536 x 1536
#define WS_HH_L0R  2752512
#define WS_HH_L1   5111808    // ends at 7471104 == sizeof(g_ws)
// fp16 arena offsets (rows x 2048, [Wh|Wh] duplicated)
#define WF_IH_L1   0
#define WF_IH_L1R  3145728
#define WF_FC1     6291456

// ============================================================================
// PTX helpers (baseline sm_80+ features; valid on .target sm_103)
// ============================================================================
__device__ __forceinline__ uint32_t smem_u32(const void* p) {
    uint32_t a;
    asm("{ .reg .u64 t; cvta.to.shared.u64 t, %1; cvt.u32.u64 %0, t; }" : "=r"(a) : "l"(p));
    return a;
}
__device__ __forceinline__ void cp16(uint32_t s, const void* g) {
    asm volatile("cp.async.cg.shared.global [%0], [%1], 16;" :: "r"(s), "l"(g));
}
__device__ __forceinline__ void ldsm4(uint32_t* r, uint32_t a) {
    asm volatile("ldmatrix.sync.aligned.m8n8.x4.shared.b16 {%0,%1,%2,%3}, [%4];"
                 : "=r"(r[0]), "=r"(r[1]), "=r"(r[2]), "=r"(r[3]) : "r"(a));
}
template<int F16>
__device__ __forceinline__ void mma_any(float* d, const uint32_t* a, uint32_t b0, uint32_t b1) {
    if (F16) {
        asm volatile("mma.sync.aligned.m16n8k16.row.col.f32.f16.f16.f32 "
                     "{%0,%1,%2,%3}, {%4,%5,%6,%7}, {%8,%9}, {%0,%1,%2,%3};"
                     : "+f"(d[0]), "+f"(d[1]), "+f"(d[2]), "+f"(d[3])
                     : "r"(a[0]), "r"(a[1]), "r"(a[2]), "r"(a[3]), "r"(b0), "r"(b1));
    } else {
        asm volatile("mma.sync.aligned.m16n8k16.row.col.f32.bf16.bf16.f32 "
                     "{%0,%1,%2,%3}, {%4,%5,%6,%7}, {%8,%9}, {%0,%1,%2,%3};"
                     : "+f"(d[0]), "+f"(d[1]), "+f"(d[2]), "+f"(d[3])
                     : "r"(a[0]), "r"(a[1]), "r"(a[2]), "r"(a[3]), "r"(b0), "r"(b1));
    }
}

__device__ __forceinline__ float sigmoidf_(float x) { return 1.f / (1.f + expf(-x)); }
__device__ __forceinline__ void split_bf16(float v, __nv_bfloat16& h, __nv_bfloat16& l) {
    h = __float2bfloat16(v);
    l = __float2bfloat16(v - __bfloat162float(h));
}
__device__ __forceinline__ void split_fp16(float v, __half& h, __half& l) {
    h = __float2half(v);
    l = __float2half(v - __half2float(h));
}

// ============================================================================
// Pipelined 16-bit GEMM: C = A' @ W'^T + bias (fp32 accum), virtual-stacked A.
// A' column k: seg = k>>kshift; seg < seghi -> Ahi[k & kmask], else Alo.
// W: [N, ldw] physical. 128x128x64 tiles, 3-stage cp.async, 8 warps (64x32).
// F16 selects fp16 vs bf16 MMA (data is typeless 16-bit to the loader).
// ============================================================================
struct MOp {
    const __nv_bfloat16 *Ahi, *Alo;
    const __nv_bfloat16 *W;
    const float *bias;
    float *C;
    int lda;
    int koff;
    int seghi;
};

#define STAGE_B 32768
#define SMEM_SZ (3 * STAGE_B)

__device__ __forceinline__ void prefetch_stage(const MOp& op, uint32_t sb, int c,
                                               int bm, int bn, int ldw,
                                               int kshift, int kmask, int tid)
{
    const int st = c % 3;
    const uint32_t abase = sb + st * STAGE_B;
    const uint32_t wbase = abase + 16384;
    const int kc0 = c * 64;
#pragma unroll
    for (int i = 0; i < 4; i++) {
        int v = tid + i * 256;
        int row = v >> 3, ch = v & 7;
        int kg  = op.koff + kc0 + ch * 8;
        int seg = kg >> kshift;
        int off = kg & kmask;
        const __nv_bfloat16* g = (seg < op.seghi ? op.Ahi : op.Alo)
                               + (size_t)(bm + row) * op.lda + off;
        cp16(abase + row * 128 + ((ch ^ (row & 7)) << 4), g);
    }
#pragma unroll
    for (int i = 0; i < 4; i++) {
        int v = tid + i * 256;
        int row = v >> 3, ch = v & 7;
        const __nv_bfloat16* g = op.W + (size_t)(bn + row) * ldw + kc0 + ch * 8;
        cp16(wbase + row * 128 + ((ch ^ (row & 7)) << 4), g);
    }
    asm volatile("cp.async.commit_group;");
}

template<int F16>
__global__ void __launch_bounds__(256, 2) mma_gemm(MOp op0, MOp op1,
                                                   int ldw, int ldc, int K, int kshift)
{
    extern __shared__ char smem[];
    MOp op = (blockIdx.z == 0) ? op0 : op1;
    const uint32_t sb = smem_u32(smem);
    const int kmask = (kshift >= 30) ? 0x3FFFFFFF : ((1 << kshift) - 1);
    const int tid  = threadIdx.x;
    const int wid  = tid >> 5;
    const int lane = tid & 31;
    const int bm = blockIdx.y * 128;
    const int bn = blockIdx.x * 128;
    const int wm = (wid >> 2) * 64;
    const int wn = (wid & 3) * 32;

    float acc[4][4][4];
#pragma unroll
    for (int i = 0; i < 4; i++)
#pragma unroll
        for (int j = 0; j < 4; j++)
#pragma unroll
            for (int r = 0; r < 4; r++) acc[i][j][r] = 0.f;

    const int nc = K >> 6;

    prefetch_stage(op, sb, 0, bm, bn, ldw, kshift, kmask, tid);
    if (nc > 1) prefetch_stage(op, sb, 1, bm, bn, ldw, kshift, kmask, tid);

    for (int c = 0; c < nc; c++) {
        if (c + 2 < nc) {
            prefetch_stage(op, sb, c + 2, bm, bn, ldw, kshift, kmask, tid);
            asm volatile("cp.async.wait_group 2;");
        } else if (c + 1 < nc) {
            asm volatile("cp.async.wait_group 1;");
        } else {
            asm volatile("cp.async.wait_group 0;");
        }
        __syncthreads();

        const int st = c % 3;
        const uint32_t abase = sb + st * STAGE_B;
        const uint32_t wbase = abase + 16384;

#pragma unroll
        for (int kk = 0; kk < 4; kk++) {
            uint32_t a[4][4], b[2][4];
#pragma unroll
            for (int mf = 0; mf < 4; mf++) {
                int r   = wm + mf * 16 + ((lane >> 3) & 1) * 8 + (lane & 7);
                int cch = kk * 2 + (lane >> 4);
                ldsm4(a[mf], abase + r * 128 + ((cch ^ (r & 7)) << 4));
            }
#pragma unroll
            for (int nf = 0; nf < 2; nf++) {
                int r   = wn + nf * 16 + ((lane >> 4) & 1) * 8 + (lane & 7);
                int cch = kk * 2 + ((lane >> 3) & 1);
                ldsm4(b[nf], wbase + r * 128 + ((cch ^ (r & 7)) << 4));
            }
#pragma unroll
            for (int mf = 0; mf < 4; mf++)
#pragma unroll
                for (int nt = 0; nt < 4; nt++)
                    mma_any<F16>(acc[mf][nt], a[mf],
                                 b[nt >> 1][(nt & 1) * 2], b[nt >> 1][(nt & 1) * 2 + 1]);
        }
        __syncthreads();
    }

#pragma unroll
    for (int mf = 0; mf < 4; mf++) {
        int row = bm + wm + mf * 16 + (lane >> 2);
#pragma unroll
        for (int nt = 0; nt < 4; nt++) {
            int col = bn + wn + nt * 8 + (lane & 3) * 2;
            float b0 = op.bias[col], b1 = op.bias[col + 1];
            float2 v0 = make_float2(acc[mf][nt][0] + b0, acc[mf][nt][1] + b1);
            float2 v1 = make_float2(acc[mf][nt][2] + b0, acc[mf][nt][3] + b1);
            *(float2*)(op.C + (size_t)row * ldc + col) = v0;
            *(float2*)(op.C + (size_t)(row + 8) * ldc + col) = v1;
        }
    }
}

// ============================================================================
// init: zero all state in one launch
// ============================================================================
#define ZF1 (2 * BH)
#define ZF2 (ZF1 + BH)
#define ZF3 (ZF2 + 1536)
#define ZB1 (2 * BH)
#define ZB2 (ZB1 + 2 * BH)
#define ZB3 (ZB2 + BH)
#define ZB4 (ZB3 + BH)
#define ZTOT (ZF3 + ZB4)

__global__ void zero_all(void)
{
    long long i = (long long)blockIdx.x * blockDim.x + threadIdx.x;
    if (i >= ZTOT) return;
    if (i < ZF3) {
        if (i < ZF1)      g_h[i] = 0.f;
        else if (i < ZF2) g_h1[i - ZF1] = 0.f;
        else              g_zb[i - ZF2] = 0.f;
    } else {
        long long k = i - ZF3;
        __nv_bfloat16 z = __float2bfloat16(0.f);
        if (k < ZB1)      g_hh[k] = z;
        else if (k < ZB2) g_hl[k - ZB1] = z;
        else if (k < ZB3) g_h1h[k - ZB2] = z;
        else              g_h1l[k - ZB3] = z;
    }
}

// ============================================================================
// conversion: all stacking jobs in one launch. Per-seg mode: 0=hi, 1=lo, 2=zero.
// f16 flag selects fp16 output (2-term path) vs bf16 (3-term path).
// ============================================================================
struct CvJobs {
    const float* src[9];
    void* dst[9];
    int off[10];
    int K[9], Kp[9], Kt[9], modes[9], total[9], f16[9];
};

__global__ void convert_all(CvJobs jobs)
{
    int bid = blockIdx.x;
    int ji = 0;
#pragma unroll
    for (int t = 1; t < 9; t++) ji += (bid >= jobs.off[t]);
    int i = (bid - jobs.off[ji]) * 256 + threadIdx.x;
    if (i >= jobs.total[ji]) return;
    const float* src = jobs.src[ji];
    int K = jobs.K[ji], Kp = jobs.Kp[ji], Kt = jobs.Kt[ji], modes = jobs.modes[ji];

    int row = i / Kt;
    int rem = i - row * Kt;
    int seg = rem / Kp;
    int kk  = rem - seg * Kp;
    int mode = (modes >> (2 * seg)) & 3;
    float v = (mode != 2 && kk < K) ? src[(size_t)row * K + kk] : 0.f;
    if (jobs.f16[ji]) {
        __half h = __float2half(v);
        __half o = h;
        if (mode == 1) o = __float2half(v - __half2float(h));
        ((__half*)jobs.dst[ji])[i] = o;
    } else {
        __nv_bfloat16 h = __float2bfloat16(v);
        __nv_bfloat16 o = h;
        if (mode == 1) o = __float2bfloat16(v - __bfloat162float(h));
        ((__nv_bfloat16*)jobs.dst[ji])[i] = o;
    }
}

// ============================================================================
// gate kernels
// ============================================================================
__global__ void gru_gate_l0(int s, int cur)
{
    const int idx = blockIdx.x * blockDim.x + threadIdx.x;  // over B*H
    const int dir = blockIdx.y;
    const int b = idx >> 9;
    const int j = idx & 511;
    const int t = (dir == 0) ? s : (Tt - 1 - s);

    const float* gx = (dir == 0 ? g_gxA : g_gxB) + ((size_t)b * Tt + t) * Gg;
    const float* gh = g_gh + (size_t)dir * BG + (size_t)b * Gg;
    const size_t hidx = (size_t)dir * BH + (size_t)b * Hh + j;

    float r = sigmoidf_(gx[j] + gh[j]);
    float z = sigmoidf_(gx[Hh + j] + gh[Hh + j]);
    float n = tanhf(gx[2 * Hh + j] + r * gh[2 * Hh + j]);
    float hn = (1.f - z) * n + z * g_h[hidx];
    g_h[hidx] = hn;

    __nv_bfloat16 hh, hl;
    split_bf16(hn, hh, hl);
    const size_t mo = (size_t)(cur ^ 1) * 2 * BH + hidx;
    g_hh[mo] = hh;  g_hl[mo] = hl;

    __half fh, fl;
    split_fp16(hn, fh, fl);
    const size_t yi = ((size_t)b * Tt + t) * 1024 + (size_t)dir * Hh + j;
    g_y0h[yi] = fh; g_y0l[yi] = fl;
}

__global__ void gru_gate_l1(int s, int cur)
{
    const int idx = blockIdx.x * blockDim.x + threadIdx.x;
    const int b = idx >> 9;
    const int j = idx & 511;

    const float* gx  = g_gxA + ((size_t)b * Tt + s) * Gg;
    const float* gh  = g_gh + (size_t)b * Gg;
    const float* gh2 = g_gh + (size_t)BG + (size_t)b * Gg;
    const size_t hidx = (size_t)b * Hh + j;

    float ar = gh[j] + gh2[j];
    float az = gh[Hh + j] + gh2[Hh + j];
    float an = gh[2 * Hh + j] + gh2[2 * Hh + j];
    float r = sigmoidf_(gx[j] + ar);
    float z = sigmoidf_(gx[Hh + j] + az);
    float n = tanhf(gx[2 * Hh + j] + r * an);
    float hn = (1.f - z) * n + z * g_h1[hidx];
    g_h1[hidx] = hn;

    __nv_bfloat16 hh, hl;
    split_bf16(hn, hh, hl);
    const size_t mo = (size_t)(cur ^ 1) * BH + hidx;
    g_h1h[mo] = hh;  g_h1l[mo] = hl;
}

__global__ void gate_l1b_last(const float* __restrict__ bhh)
{
    const int idx = blockIdx.x * blockDim.x + threadIdx.x;
    const int b = idx >> 9;
    const int j = idx & 511;
    const float* gx = g_gx1b + (size_t)b * Gg;
    float r = sigmoidf_(gx[j] + bhh[j]);
    float z = sigmoidf_(gx[Hh + j] + bhh[Hh + j]);
    float n = tanhf(gx[2 * Hh + j] + r * bhh[2 * Hh + j]);
    g_h1b[(size_t)b * Hh + j] = (1.f - z) * n;
}

__global__ void concat_last(void)
{
    const int idx = blockIdx.x * blockDim.x + threadIdx.x;
    const int b = idx >> 10;
    const int j = idx & 1023;
    float v = (j < Hh) ? g_h1[(size_t)b * Hh + j] : g_h1b[(size_t)b * Hh + (j - Hh)];
    __half fh, fl;
    split_fp16(v, fh, fl);
    g_lasth[(size_t)b * H2 + j] = fh;
    g_lastl[(size_t)b * H2 + j] = fl;
}

__global__ void head_kernel(const float* __restrict__ gamma, const float* __restrict__ beta,
                            const float* __restrict__ mean, const float* __restrict__ var,
                            const float* __restrict__ fc2w, const float* __restrict__ fc2b,
                            float* __restrict__ out)
{
    const int b = blockIdx.x;
    const int tid = threadIdx.x;
    __shared__ float a[256];
    __shared__ float logits[10];

    float v = g_z1[(size_t)b * 256 + tid];
    v = (v - mean[tid]) * rsqrtf(var[tid] + 1e-5f) * gamma[tid] + beta[tid];
    a[tid] = fmaxf(v, 0.f);
    __syncthreads();

    if (tid < 10) {
        float acc = fc2b[tid];
        const float* wrow = fc2w + tid * 256;
        for (int k = 0; k < 256; k++) acc = fmaf(a[k], wrow[k], acc);
        logits[tid] = acc;
    }
    __syncthreads();

    if (tid == 0) {
        float mx = logits[0];
        for (int i = 1; i < 10; i++) mx = fmaxf(mx, logits[i]);
        float s = 0.f;
        for (int i = 0; i < 10; i++) s += expf(logits[i] - mx);
        float lse = mx + logf(s);
        for (int i = 0; i < 10; i++) out[(size_t)b * 10 + i] = logits[i] - lse;
    }
}

// ============================================================================
// host-side launch
// ============================================================================
extern "C" void kernel_launch(void* const* d_in, const int* in_sizes, int n_in,
                              void* d_out, int out_size)
{
    (void)in_sizes; (void)n_in; (void)out_size;
    const float* x         = (const float*)d_in[0];
    const float* W_ih_l0   = (const float*)d_in[1];
    const float* W_hh_l0   = (const float*)d_in[2];
    const float* b_ih_l0   = (const float*)d_in[3];
    const float* b_hh_l0   = (const float*)d_in[4];
    const float* W_ih_l0r  = (const float*)d_in[5];
    const float* W_hh_l0r  = (const float*)d_in[6];
    const float* b_ih_l0r  = (const float*)d_in[7];
    const float* b_hh_l0r  = (const float*)d_in[8];
    const float* W_ih_l1   = (const float*)d_in[9];
    const float* W_hh_l1   = (const float*)d_in[10];
    const float* b_ih_l1   = (const float*)d_in[11];
    const float* b_hh_l1   = (const float*)d_in[12];
    const float* W_ih_l1r  = (const float*)d_in[13];
    const float* W_hh_l1r  = (const float*)d_in[14];
    const float* b_ih_l1r  = (const float*)d_in[15];
    const float* b_hh_l1r  = (const float*)d_in[16];
    const float* fc1_w     = (const float*)d_in[17];
    const float* fc1_b     = (const float*)d_in[18];
    const float* bn_gamma  = (const float*)d_in[19];
    const float* bn_beta   = (const float*)d_in[20];
    const float* bn_mean   = (const float*)d_in[21];
    const float* bn_var    = (const float*)d_in[22];
    const float* fc2_w     = (const float*)d_in[23];
    const float* fc2_b     = (const float*)d_in[24];
    float* out = (float*)d_out;

    float *p_gxA, *p_gxB, *p_gh, *p_gx1b, *p_z1, *p_zb;
    __nv_bfloat16 *p_xs, *p_ws, *p_hh, *p_hl, *p_h1h, *p_h1l;
    __half *p_y0h, *p_y0l, *p_lh, *p_ll, *p_wf;
    cudaGetSymbolAddress((void**)&p_gxA,  g_gxA);
    cudaGetSymbolAddress((void**)&p_gxB,  g_gxB);
    cudaGetSymbolAddress((void**)&p_gh,   g_gh);
    cudaGetSymbolAddress((void**)&p_gx1b, g_gx1b);
    cudaGetSymbolAddress((void**)&p_z1,   g_z1);
    cudaGetSymbolAddress((void**)&p_zb,   g_zb);
    cudaGetSymbolAddress((void**)&p_xs,   g_xs);
    cudaGetSymbolAddress((void**)&p_ws,   g_ws);
    cudaGetSymbolAddress((void**)&p_y0h,  g_y0h);
    cudaGetSymbolAddress((void**)&p_y0l,  g_y0l);
    cudaGetSymbolAddress((void**)&p_hh,   g_hh);
    cudaGetSymbolAddress((void**)&p_hl,   g_hl);
    cudaGetSymbolAddress((void**)&p_h1h,  g_h1h);
    cudaGetSymbolAddress((void**)&p_h1l,  g_h1l);
    cudaGetSymbolAddress((void**)&p_lh,   g_lasth);
    cudaGetSymbolAddress((void**)&p_ll,   g_lastl);
    cudaGetSymbolAddress((void**)&p_wf,   g_wf);

    cudaFuncSetAttribute(mma_gemm<0>, cudaFuncAttributeMaxDynamicSharedMemorySize, SMEM_SZ);
    cudaFuncSetAttribute(mma_gemm<1>, cudaFuncAttributeMaxDynamicSharedMemorySize, SMEM_SZ);

    const int MODES_A4 = 0 | (0 << 2) | (1 << 4) | (2 << 6);  // [hi|hi|lo|0]
    const int MODES_W4 = 0 | (1 << 2) | (0 << 4) | (2 << 6);  // [hi|lo|hi|0]
    const int MODES_W3 = 0 | (1 << 2) | (0 << 4);             // [hi|lo|hi]
    const int MODES_D2 = 0 | (0 << 2);                        // [hi|hi] (fp16 dup)

    // 0) conversions (one launch) + zero init (one launch)
    {
        CvJobs cj;
        const float* srcs[9] = { x, W_ih_l0, W_ih_l0r, W_hh_l0, W_hh_l0r,
                                 W_hh_l1, W_ih_l1, W_ih_l1r, fc1_w };
        void* dsts[9] = { p_xs, p_ws + WS_IH_L0, p_ws + WS_IH_L0R,
                          p_ws + WS_HH_L0, p_ws + WS_HH_L0R, p_ws + WS_HH_L1,
                          p_wf + WF_IH_L1, p_wf + WF_IH_L1R, p_wf + WF_FC1 };
        int Ks[9]  = { 28, 28, 28, 512, 512, 512, 1024, 1024, 1024 };
        int Kps[9] = { 32, 32, 32, 512, 512, 512, 1024, 1024, 1024 };
        int Kts[9] = { 128, 128, 128, 1536, 1536, 1536, 2048, 2048, 2048 };
        int mds[9] = { MODES_A4, MODES_W4, MODES_W4, MODES_W3, MODES_W3,
                       MODES_W3, MODES_D2, MODES_D2, MODES_D2 };
        int f16s[9] = { 0, 0, 0, 0, 0, 0, 1, 1, 1 };
        int tots[9] = { MT * 128, 1536 * 128, 1536 * 128, 1536 * 1536, 1536 * 1536,
                        1536 * 1536, 1536 * 2048, 1536 * 2048, 256 * 2048 };
        int off = 0;
        for (int i = 0; i < 9; i++) {
            cj.src[i] = srcs[i]; cj.dst[i] = dsts[i];
            cj.K[i] = Ks[i]; cj.Kp[i] = Kps[i]; cj.Kt[i] = Kts[i];
            cj.modes[i] = mds[i]; cj.total[i] = tots[i]; cj.f16[i] = f16s[i];
            cj.off[i] = off;
            off += (tots[i] + 255) / 256;
        }
        cj.off[9] = off;
        convert_all<<<off, 256>>>(cj);
        zero_all<<<(ZTOT + 255) / 256, 256>>>();
    }

    // 1) layer-0 input projections (fwd+bwd), bf16 3-term physical, K'=128
    {
        MOp f{ p_xs, p_xs, p_ws + WS_IH_L0,  b_ih_l0,  p_gxA, 128, 0, 2 };
        MOp r{ p_xs, p_xs, p_ws + WS_IH_L0R, b_ih_l0r, p_gxB, 128, 0, 2 };
        mma_gemm<0><<<dim3(Gg / 128, MT / 128, 2), 256, SMEM_SZ>>>(f, r, 128, Gg, 128, 30);
    }

    // 2) layer-0 recurrence: bf16 3-term virtual [hi|hi|lo], K'=1536
    for (int s = 0; s < Tt; s++) {
        const int cur = s & 1;
        const size_t mb = (size_t)cur * 2 * BH;
        MOp f{ p_hh + mb,      p_hl + mb,      p_ws + WS_HH_L0,  b_hh_l0,  p_gh,      512, 0, 2 };
        MOp r{ p_hh + mb + BH, p_hl + mb + BH, p_ws + WS_HH_L0R, b_hh_l0r, p_gh + BG, 512, 0, 2 };
        mma_gemm<0><<<dim3(Gg / 128, Bv / 128, 2), 256, SMEM_SZ>>>(f, r, Gg, Gg, Gg, 9);
        gru_gate_l0<<<dim3(BH / 256, 2), 256>>>(s, cur);
    }

    // 3) layer-1 input projection: fp16 2-term [y0hi|y0lo] x [Wh|Wh], K'=2048
    {
        MOp f{ (const __nv_bfloat16*)p_y0h, (const __nv_bfloat16*)p_y0l,
               (const __nv_bfloat16*)(p_wf + WF_IH_L1), b_ih_l1, p_gxA, 1024, 0, 1 };
        mma_gemm<1><<<dim3(Gg / 128, MT / 128, 1), 256, SMEM_SZ>>>(f, f, 2048, Gg, 2048, 10);
    }

    // 4) layer-1 bwd input projection at t=T-1 only (fp16 2-term)
    {
        MOp f{ (const __nv_bfloat16*)(p_y0h + (size_t)(Tt - 1) * 1024),
               (const __nv_bfloat16*)(p_y0l + (size_t)(Tt - 1) * 1024),
               (const __nv_bfloat16*)(p_wf + WF_IH_L1R), b_ih_l1r, p_gx1b,
               Tt * 1024, 0, 1 };
        mma_gemm<1><<<dim3(Gg / 128, Bv / 128, 1), 256, SMEM_SZ>>>(f, f, 2048, Gg, 2048, 10);
    }
    gate_l1b_last<<<BH / 256, 256>>>(b_hh_l1r);

    // 5) layer-1 fwd recurrence: bf16 3-term, split-K (two 768-halves)
    for (int s = 0; s < Tt; s++) {
        const int cur = s & 1;
        const size_t mb = (size_t)cur * BH;
        MOp h0{ p_h1h + mb, p_h1l + mb, p_ws + WS_HH_L1,       b_hh_l1, p_gh,      512, 0,   2 };
        MOp h1{ p_h1h + mb, p_h1l + mb, p_ws + WS_HH_L1 + 768, p_zb,    p_gh + BG, 512, 768, 2 };
        mma_gemm<0><<<dim3(Gg / 128, Bv / 128, 2), 256, SMEM_SZ>>>(h0, h1, Gg, Gg, 768, 9);
        gru_gate_l1<<<BH / 256, 256>>>(s, cur);
    }

    // 6) head: concat -> fc1 (fp16 2-term) -> bn/relu/fc2/log_softmax
    concat_last<<<(Bv * H2) / 256, 256>>>();
    {
        MOp f{ (const __nv_bfloat16*)p_lh, (const __nv_bfloat16*)p_ll,
               (const __nv_bfloat16*)(p_wf + WF_FC1), fc1_b, p_z1, 1024, 0, 1 };
        mma_gemm<1><<<dim3(256 / 128, Bv / 128, 1), 256, SMEM_SZ>>>(f, f, 2048, 256, 2048, 10);
    }
    head_kernel<<<Bv, 256>>>(bn_gamma, bn_beta, bn_mean, bn_var, fc2_w, fc2_b, out);
}